// round 14
// baseline (speedup 1.0000x reference)
#include <cuda_runtime.h>
#include <cstdint>

// ---------------------------------------------------------------------------
// EncoderGRU: bidirectional GRU, SEQ=4096, HIDDEN=EMBED=1024.
//
//   Phase 1+2 (one kernel): GI[t] = w_ih @ emb[tok[t]] + b_ih, fp32 SIMT GEMM,
//            inline token prep + recurrent-state reset by block (0,0).
//   Phase 3: persistent kernel, 128 CTAs (64 fwd / 64 bwd), each CTA owns 16
//            hidden units. NEW mapping: warp w owns units {2w, 2w+1} with all
//            3 gates (6 rows; 4 in registers, 2 in smem). The butterfly
//            reduce leaves full sums in every lane, so lanes 0/1 of each warp
//            compute their unit's gates IN-WARP: no sums smem, no first
//            barrier, no warp-0 serialization. One __syncthreads per step
//            (h stores done) before the thread-0 release.
//            Sync protocol (r12/r13-proven): producer red.release.gpu after
//            CTA barrier; consumer ld.acquire.gpu poll + ~180cyc clock spin.
//            Matvec: packed fma.rn.f32x2 (r13-proven).
// ---------------------------------------------------------------------------

#define VOCAB   50257
#define HID     1024
#define SEQ     4096
#define NROWS   (SEQ + 2)       // 4098: +SOS row, +EOS row
#define GATES   3072

#define NCTA    128             // persistent grid (1 CTA/SM)
#define UNITS   16              // hidden units per CTA (64 CTAs/dir * 16 = 1024)
#define GT      256             // threads in recurrent kernel
#define RPW     6               // rows per warp (3 gates x 2 units)
#define RREG    4               // rows per warp held in registers (gates r,z)
#define RSM     2               // rows per warp streamed from smem (gate n)

// ---- global scratch (allocation-free: __device__ globals) ----
__device__ __align__(16)  float g_GI[(size_t)NROWS * GATES];    // ~50 MB
__device__ __align__(16)  float g_h[2][2][HID];                 // [dir][buf][unit]
__device__ __align__(128) int   g_cnt[2][32];                   // one 128B line per dir

// acquire-load: ordering + data in one instruction (pairs with red.release)
__device__ __forceinline__ int ld_acq(const int* p) {
    int v;
    asm volatile("ld.acquire.gpu.global.b32 %0, [%1];"
                 : "=r"(v) : "l"(p) : "memory");
    return v;
}
// release-reduction: publishes +1 with release semantics (cumulative through
// the preceding bar.sync -> covers the CTA's prior h stores)
__device__ __forceinline__ void red_rel_add(int* p) {
    asm volatile("red.release.gpu.global.add.u32 [%0], 1;"
                 :: "l"(p) : "memory");
}
// packed dual-fp32 FMA: d = a*b + d (elementwise on 2 packed floats)
__device__ __forceinline__ void fma_f32x2(unsigned long long& d,
                                          unsigned long long a,
                                          unsigned long long b) {
    asm("fma.rn.f32x2 %0, %1, %2, %3;" : "=l"(d) : "l"(a), "l"(b), "l"(d));
}
__device__ __forceinline__ float f32x2_hsum(unsigned long long v) {
    float lo, hi;
    asm("mov.b64 {%0, %1}, %2;" : "=f"(lo), "=f"(hi) : "l"(v));
    return lo + hi;
}

// Calibrated busy-wait: no memory traffic, bounded duration (SM clock cycles).
__device__ __forceinline__ void spin_cycles(long long n) {
    long long lim = clock64() + n;
    while (clock64() < lim) { }
}

// ---------------------------------------------------------------------------
// Phase 1+2: GI GEMM with inline token prep + state reset.
// C[m][n] = sum_k emb[tok[m]][k] * w_ih[n][k] + b_ih[n]
// BM=BN=128, BK=8, 256 threads, 8x8 microtile per thread.
// ---------------------------------------------------------------------------
#define BM 128
#define BN 128
#define BK 8

__global__ void __launch_bounds__(256) gi_gemm_kernel(
    const void*  __restrict__ tok_raw,
    const float* __restrict__ emb,
    const float* __restrict__ w_ih,
    const float* __restrict__ b_ih) {

    __shared__ float As[BK][BM];
    __shared__ float Bs[BK][BN];
    __shared__ int   mode64_sh;

    const int tid  = threadIdx.x;
    const int m0   = blockIdx.y * BM;
    const int n0   = blockIdx.x * BN;
    const int lrow = tid >> 1;          // 0..127
    const int lk   = (tid & 1) * 4;     // 0 or 4
    const int tx   = tid & 15;
    const int ty   = tid >> 4;

    // state reset (fresh every launch / graph replay) -- block (0,0) only
    if (blockIdx.x == 0 && blockIdx.y == 0) {
        for (int i = tid; i < 2 * 2 * HID; i += 256) ((float*)g_h)[i] = 0.f;
        if (tid < 64) ((int*)g_cnt)[tid] = 0;
    }

    // token dtype detection (per block; 8 loads, trivial)
    if (tid == 0) {
        // Genuine int64 tokens: every value < VOCAB (high word 0).
        // int32 data misread as int64: some 64-bit word >= VOCAB w.h.p.
        const unsigned long long* p = (const unsigned long long*)tok_raw;
        int m = 1;
        #pragma unroll
        for (int i = 0; i < 8; i++)
            if (p[i] >= (unsigned long long)VOCAB) m = 0;
        mode64_sh = m;
    }
    __syncthreads();
    const int mode64 = mode64_sh;

    // inline token fetch for this block's A row
    const int m = m0 + lrow;
    const float* arow_ptr = nullptr;
    if (m < NROWS) {
        int tok;
        if (m == SEQ)          tok = 0;   // SOS
        else if (m == SEQ + 1) tok = 1;   // EOS
        else tok = mode64 ? (int)((const long long*)tok_raw)[m]
                          : ((const int*)tok_raw)[m];
        arow_ptr = emb + (size_t)tok * HID;
    }
    const float* brow_ptr = w_ih + (size_t)(n0 + lrow) * HID;

    float acc[8][8];
    #pragma unroll
    for (int i = 0; i < 8; i++)
        #pragma unroll
        for (int j = 0; j < 8; j++) acc[i][j] = 0.f;

    for (int k0 = 0; k0 < HID; k0 += BK) {
        float4 a4 = make_float4(0.f, 0.f, 0.f, 0.f);
        if (arow_ptr) a4 = *(const float4*)(arow_ptr + k0 + lk);
        float4 b4 = *(const float4*)(brow_ptr + k0 + lk);
        As[lk + 0][lrow] = a4.x; As[lk + 1][lrow] = a4.y;
        As[lk + 2][lrow] = a4.z; As[lk + 3][lrow] = a4.w;
        Bs[lk + 0][lrow] = b4.x; Bs[lk + 1][lrow] = b4.y;
        Bs[lk + 2][lrow] = b4.z; Bs[lk + 3][lrow] = b4.w;
        __syncthreads();

        #pragma unroll
        for (int kk = 0; kk < BK; kk++) {
            float ra[8], rb[8];
            *(float4*)&ra[0] = *(const float4*)&As[kk][ty * 8];
            *(float4*)&ra[4] = *(const float4*)&As[kk][ty * 8 + 4];
            *(float4*)&rb[0] = *(const float4*)&Bs[kk][tx * 8];
            *(float4*)&rb[4] = *(const float4*)&Bs[kk][tx * 8 + 4];
            #pragma unroll
            for (int i = 0; i < 8; i++)
                #pragma unroll
                for (int j = 0; j < 8; j++)
                    acc[i][j] += ra[i] * rb[j];
        }
        __syncthreads();
    }

    float bias[8];
    *(float4*)&bias[0] = *(const float4*)(b_ih + n0 + tx * 8);
    *(float4*)&bias[4] = *(const float4*)(b_ih + n0 + tx * 8 + 4);

    #pragma unroll
    for (int i = 0; i < 8; i++) {
        int mm = m0 + ty * 8 + i;
        if (mm < NROWS) {
            float* gp = g_GI + (size_t)mm * GATES + n0 + tx * 8;
            float4 v0 = make_float4(acc[i][0] + bias[0], acc[i][1] + bias[1],
                                    acc[i][2] + bias[2], acc[i][3] + bias[3]);
            float4 v1 = make_float4(acc[i][4] + bias[4], acc[i][5] + bias[5],
                                    acc[i][6] + bias[6], acc[i][7] + bias[7]);
            *(float4*)gp       = v0;
            *(float4*)(gp + 4) = v1;
        }
    }
}

// ---------------------------------------------------------------------------
// Phase 3: persistent recurrent kernel (warp-local gates, f32x2 matvec).
// Warp w owns units {u0+2w, u0+2w+1}. Local row r (0..5): gate g = r>>1,
// unit offset e = r&1 -> global row g*1024 + u0 + 2w + e.
// Rows 0..3 (gates r,z) in registers; rows 4..5 (gate n) in smem.
// ---------------------------------------------------------------------------
__global__ void __launch_bounds__(GT, 1) gru_seq_kernel(
    const float* __restrict__ w_hh,
    const float* __restrict__ b_hh,
    float* __restrict__ out) {

    extern __shared__ float smem[];
    float* wsh = smem;                  // 16 rows (2/warp, gate n) * HID

    const int cta  = blockIdx.x;
    const int dir  = cta >> 6;          // 0 = forward, 1 = backward
    const int lcta = cta & 63;
    const int u0   = lcta * UNITS;
    const int warp = threadIdx.x >> 5;
    const int lane = threadIdx.x & 31;

    // --- smem rows (gate n): mrow = warp*2 + e -> grow = 2048 + u0 + 2w + e
    for (int i = threadIdx.x; i < RSM * 8 * HID; i += GT) {
        int mrow = i >> 10;             // 0..15
        int c    = i & (HID - 1);
        int grow = 2 * HID + u0 + 2 * (mrow >> 1) + (mrow & 1);
        wsh[i] = w_hh[(size_t)grow * HID + c];
    }

    // --- register rows (gates r,z): row r -> (g = r>>1, e = r&1)
    ulonglong2 wreg[RREG][8];
    #pragma unroll
    for (int r = 0; r < RREG; r++) {
        const int grow = (r >> 1) * HID + u0 + 2 * warp + (r & 1);
        const float* gw = w_hh + (size_t)grow * HID + lane * 4;
        #pragma unroll
        for (int j = 0; j < 8; j++)
            wreg[r][j] = *(const ulonglong2*)(gw + j * 128);
    }

    // --- biases in registers (lanes 0/1 own unit u0+2w+lane)
    float b_r = 0.f, b_z = 0.f, b_n = 0.f;
    const int myu = u0 + 2 * warp + lane;   // valid for lane < 2
    if (lane < 2) {
        b_r = b_hh[myu];
        b_z = b_hh[HID + myu];
        b_n = b_hh[2 * HID + myu];
    }
    __syncthreads();

    const float* wp = wsh + (warp * RSM) * HID + lane * 4;  // gate-n rows
    int* cnt_p = &g_cnt[dir][0];

    float hprev = 0.f;                  // lanes 0/1 only

    for (int s = 0; s <= SEQ; s++) {
        const int t     = dir ? (SEQ - s) : (s - 1);
        const int girow = (s == 0) ? (SEQ + dir) : t;

        // gi prefetch (lanes 0/1 of every warp; independent of h)
        float gir = 0.f, giz = 0.f, gin = 0.f;
        if (lane < 2) {
            const float* gp = g_GI + (size_t)girow * GATES + myu;
            gir = __ldg(gp);
            giz = __ldg(gp + HID);
            gin = __ldg(gp + 2 * HID);
        }

        // Wait until all 64 CTAs of this direction finished step s-1.
        // EVERY thread polls with an ACQUIRE load (broadcast 4B sector);
        // ~180cyc spin backoff rides the worst-of-64 tail.
        if (s > 0) {
            const int need = s << 6;    // 64 * s
            if (ld_acq(cnt_p) < need) {
                do { spin_cycles(180); } while (ld_acq(cnt_p) < need);
            }
        }

        // load broadcast h as packed pairs (L2)
        const ulonglong2* hp = (const ulonglong2*)(&g_h[dir][s & 1][0]) + lane;
        ulonglong2 h2[8];
        #pragma unroll
        for (int j = 0; j < 8; j++) h2[j] = __ldcg(hp + 32 * j);

        // 6 dot products per warp in packed f32x2
        unsigned long long accp[RPW] = {0ull, 0ull, 0ull, 0ull, 0ull, 0ull};
        #pragma unroll
        for (int j = 0; j < 8; j++) {
            const ulonglong2 hv = h2[j];
            #pragma unroll
            for (int r = 0; r < RREG; r++) {
                fma_f32x2(accp[r], wreg[r][j].x, hv.x);
                fma_f32x2(accp[r], wreg[r][j].y, hv.y);
            }
            #pragma unroll
            for (int r = 0; r < RSM; r++) {
                const ulonglong2 wv = *(const ulonglong2*)(wp + r * HID + j * 128);
                fma_f32x2(accp[RREG + r], wv.x, hv.x);
                fma_f32x2(accp[RREG + r], wv.y, hv.y);
            }
        }
        // butterfly reduce: EVERY lane ends with the full sum of each row
        float sum[RPW];
        #pragma unroll
        for (int r = 0; r < RPW; r++) {
            float v = f32x2_hsum(accp[r]);
            v += __shfl_xor_sync(0xffffffffu, v, 16);
            v += __shfl_xor_sync(0xffffffffu, v, 8);
            v += __shfl_xor_sync(0xffffffffu, v, 4);
            v += __shfl_xor_sync(0xffffffffu, v, 2);
            v += __shfl_xor_sync(0xffffffffu, v, 1);
            sum[r] = v;
        }

        // warp-local gates: lane e handles unit u0+2w+e (rows {e, 2+e, 4+e})
        float hn = 0.f;
        if (lane < 2) {
            float ar = gir + sum[lane]     + b_r;
            float az = giz + sum[2 + lane] + b_z;
            float rg = __fdividef(1.f, 1.f + __expf(-ar));
            float zg = __fdividef(1.f, 1.f + __expf(-az));
            float an = gin + rg * (sum[4 + lane] + b_n);
            float en = __expf(-2.f * an);
            float ng = __fdividef(1.f - en, 1.f + en);   // tanh(an)
            hn = (1.f - zg) * ng + zg * hprev;
            hprev = hn;
            __stcg(&g_h[dir][(s + 1) & 1][myu], hn);
        }
        __syncthreads();                // all 16 h stores done before release
        if (threadIdx.x == 0) {
            red_rel_add(cnt_p);         // release-REDG: publish h + count
        }
        // out stores AFTER the publish (never read in-kernel)
        if (lane < 2 && s >= 1) {
            out[(size_t)HID + (size_t)t * (2 * HID) + dir * HID + myu] = hn;
            if (dir == 1 && t == 0) out[myu] = hn;   // h_b = hs_b[0]
        }
    }
}

// ---------------------------------------------------------------------------
// launch
// ---------------------------------------------------------------------------
extern "C" void kernel_launch(void* const* d_in, const int* in_sizes, int n_in,
                              void* d_out, int out_size) {
    const void*  tokens = d_in[0];
    const float* emb    = (const float*)d_in[1];
    const float* w_ih   = (const float*)d_in[2];
    const float* w_hh   = (const float*)d_in[3];
    const float* b_ih   = (const float*)d_in[4];
    const float* b_hh   = (const float*)d_in[5];
    float* out = (float*)d_out;

    const int smem_bytes = (RSM * 8 * HID + 16) * (int)sizeof(float);
    cudaFuncSetAttribute(gru_seq_kernel,
                         cudaFuncAttributeMaxDynamicSharedMemorySize,
                         smem_bytes);

    dim3 ggrid(GATES / BN, (NROWS + BM - 1) / BM);
    gi_gemm_kernel<<<ggrid, 256>>>(tokens, emb, w_ih, b_ih);

    gru_seq_kernel<<<NCTA, GT, smem_bytes>>>(w_hh, b_hh, out);
}

// round 15
// speedup vs baseline: 1.0604x; 1.0604x over previous
#include <cuda_runtime.h>
#include <cstdint>

// ---------------------------------------------------------------------------
// EncoderGRU: bidirectional GRU, SEQ=4096, HIDDEN=EMBED=1024.
//
//   Phase 1+2 (one kernel): GI[t] = w_ih @ emb[tok[t]] + b_ih, fp32 SIMT GEMM,
//            inline token prep + recurrent-state reset by block (0,0).
//   Phase 3: persistent kernel, 128 CTAs (64 fwd / 64 bwd), each CTA owns 16
//            hidden units (48 w_hh rows; 4/warp in registers, 2/warp in smem).
//            r13 base (proven fastest). Changes this round:
//              - publish: warp-0-scoped 32-thread NAMED barrier (BAR-based
//                cumulativity, same mechanism as __syncthreads) before the
//                lane-0 red.release -- the 256-thread bar#2 is gone; warps
//                1-7 go straight from the sums barrier to the next poll.
//              - spin quantum 180 -> 90 cyc (rides the worst-of-64 tail).
//            Matvec: packed fma.rn.f32x2. Consumer: ld.acquire.gpu poll.
// ---------------------------------------------------------------------------

#define VOCAB   50257
#define HID     1024
#define SEQ     4096
#define NROWS   (SEQ + 2)       // 4098: +SOS row, +EOS row
#define GATES   3072

#define NCTA    128             // persistent grid (1 CTA/SM)
#define UNITS   16              // hidden units per CTA (64 CTAs/dir * 16 = 1024)
#define RPC     48              // weight rows per CTA (3 gates * 16 units)
#define GT      256             // threads in recurrent kernel
#define RPW     6               // rows per warp (8 warps * 6 = 48)
#define RREG    4               // rows per warp held in registers
#define RSM     2               // rows per warp streamed from smem (RPW-RREG)

// ---- global scratch (allocation-free: __device__ globals) ----
__device__ __align__(16)  float g_GI[(size_t)NROWS * GATES];    // ~50 MB
__device__ __align__(16)  float g_h[2][2][HID];                 // [dir][buf][unit]
__device__ __align__(128) int   g_cnt[2][32];                   // one 128B line per dir

// acquire-load: ordering + data in one instruction (pairs with red.release)
__device__ __forceinline__ int ld_acq(const int* p) {
    int v;
    asm volatile("ld.acquire.gpu.global.b32 %0, [%1];"
                 : "=r"(v) : "l"(p) : "memory");
    return v;
}
// release-reduction: publishes +1 with release semantics (cumulative through
// the preceding BAR -> covers warp 0's prior h stores)
__device__ __forceinline__ void red_rel_add(int* p) {
    asm volatile("red.release.gpu.global.add.u32 [%0], 1;"
                 :: "l"(p) : "memory");
}
// packed dual-fp32 FMA: d = a*b + d (elementwise on 2 packed floats)
__device__ __forceinline__ void fma_f32x2(unsigned long long& d,
                                          unsigned long long a,
                                          unsigned long long b) {
    asm("fma.rn.f32x2 %0, %1, %2, %3;" : "=l"(d) : "l"(a), "l"(b), "l"(d));
}
__device__ __forceinline__ float f32x2_hsum(unsigned long long v) {
    float lo, hi;
    asm("mov.b64 {%0, %1}, %2;" : "=f"(lo), "=f"(hi) : "l"(v));
    return lo + hi;
}

// Calibrated busy-wait: no memory traffic, bounded duration (SM clock cycles).
__device__ __forceinline__ void spin_cycles(long long n) {
    long long lim = clock64() + n;
    while (clock64() < lim) { }
}

// ---------------------------------------------------------------------------
// Phase 1+2: GI GEMM with inline token prep + state reset.
// C[m][n] = sum_k emb[tok[m]][k] * w_ih[n][k] + b_ih[n]
// BM=BN=128, BK=8, 256 threads, 8x8 microtile per thread.
// ---------------------------------------------------------------------------
#define BM 128
#define BN 128
#define BK 8

__global__ void __launch_bounds__(256) gi_gemm_kernel(
    const void*  __restrict__ tok_raw,
    const float* __restrict__ emb,
    const float* __restrict__ w_ih,
    const float* __restrict__ b_ih) {

    __shared__ float As[BK][BM];
    __shared__ float Bs[BK][BN];
    __shared__ int   mode64_sh;

    const int tid  = threadIdx.x;
    const int m0   = blockIdx.y * BM;
    const int n0   = blockIdx.x * BN;
    const int lrow = tid >> 1;          // 0..127
    const int lk   = (tid & 1) * 4;     // 0 or 4
    const int tx   = tid & 15;
    const int ty   = tid >> 4;

    // state reset (fresh every launch / graph replay) -- block (0,0) only
    if (blockIdx.x == 0 && blockIdx.y == 0) {
        for (int i = tid; i < 2 * 2 * HID; i += 256) ((float*)g_h)[i] = 0.f;
        if (tid < 64) ((int*)g_cnt)[tid] = 0;
    }

    // token dtype detection (per block; 8 loads, trivial)
    if (tid == 0) {
        // Genuine int64 tokens: every value < VOCAB (high word 0).
        // int32 data misread as int64: some 64-bit word >= VOCAB w.h.p.
        const unsigned long long* p = (const unsigned long long*)tok_raw;
        int m = 1;
        #pragma unroll
        for (int i = 0; i < 8; i++)
            if (p[i] >= (unsigned long long)VOCAB) m = 0;
        mode64_sh = m;
    }
    __syncthreads();
    const int mode64 = mode64_sh;

    // inline token fetch for this block's A row
    const int m = m0 + lrow;
    const float* arow_ptr = nullptr;
    if (m < NROWS) {
        int tok;
        if (m == SEQ)          tok = 0;   // SOS
        else if (m == SEQ + 1) tok = 1;   // EOS
        else tok = mode64 ? (int)((const long long*)tok_raw)[m]
                          : ((const int*)tok_raw)[m];
        arow_ptr = emb + (size_t)tok * HID;
    }
    const float* brow_ptr = w_ih + (size_t)(n0 + lrow) * HID;

    float acc[8][8];
    #pragma unroll
    for (int i = 0; i < 8; i++)
        #pragma unroll
        for (int j = 0; j < 8; j++) acc[i][j] = 0.f;

    for (int k0 = 0; k0 < HID; k0 += BK) {
        float4 a4 = make_float4(0.f, 0.f, 0.f, 0.f);
        if (arow_ptr) a4 = *(const float4*)(arow_ptr + k0 + lk);
        float4 b4 = *(const float4*)(brow_ptr + k0 + lk);
        As[lk + 0][lrow] = a4.x; As[lk + 1][lrow] = a4.y;
        As[lk + 2][lrow] = a4.z; As[lk + 3][lrow] = a4.w;
        Bs[lk + 0][lrow] = b4.x; Bs[lk + 1][lrow] = b4.y;
        Bs[lk + 2][lrow] = b4.z; Bs[lk + 3][lrow] = b4.w;
        __syncthreads();

        #pragma unroll
        for (int kk = 0; kk < BK; kk++) {
            float ra[8], rb[8];
            *(float4*)&ra[0] = *(const float4*)&As[kk][ty * 8];
            *(float4*)&ra[4] = *(const float4*)&As[kk][ty * 8 + 4];
            *(float4*)&rb[0] = *(const float4*)&Bs[kk][tx * 8];
            *(float4*)&rb[4] = *(const float4*)&Bs[kk][tx * 8 + 4];
            #pragma unroll
            for (int i = 0; i < 8; i++)
                #pragma unroll
                for (int j = 0; j < 8; j++)
                    acc[i][j] += ra[i] * rb[j];
        }
        __syncthreads();
    }

    float bias[8];
    *(float4*)&bias[0] = *(const float4*)(b_ih + n0 + tx * 8);
    *(float4*)&bias[4] = *(const float4*)(b_ih + n0 + tx * 8 + 4);

    #pragma unroll
    for (int i = 0; i < 8; i++) {
        int mm = m0 + ty * 8 + i;
        if (mm < NROWS) {
            float* gp = g_GI + (size_t)mm * GATES + n0 + tx * 8;
            float4 v0 = make_float4(acc[i][0] + bias[0], acc[i][1] + bias[1],
                                    acc[i][2] + bias[2], acc[i][3] + bias[3]);
            float4 v1 = make_float4(acc[i][4] + bias[4], acc[i][5] + bias[5],
                                    acc[i][6] + bias[6], acc[i][7] + bias[7]);
            *(float4*)gp       = v0;
            *(float4*)(gp + 4) = v1;
        }
    }
}

// ---------------------------------------------------------------------------
// Phase 3: persistent recurrent kernel (f32x2 matvec, warp-0 BAR publish).
// Weight rows per warp: rows 0..3 in registers, rows 4..5 in smem.
// Global row for local row rr (0..47): ((rr>>4)<<10) + u0 + (rr&15).
// ---------------------------------------------------------------------------
__global__ void __launch_bounds__(GT, 1) gru_seq_kernel(
    const float* __restrict__ w_hh,
    const float* __restrict__ b_hh,
    float* __restrict__ out) {

    extern __shared__ float smem[];
    float* wsh  = smem;                 // 16 rows (2/warp) * HID
    float* bsh  = smem + (RSM * 8) * HID;   // RPC biases
    float* sums = bsh + RPC;            // RPC partial sums

    const int cta  = blockIdx.x;
    const int dir  = cta >> 6;          // 0 = forward, 1 = backward
    const int lcta = cta & 63;
    const int u0   = lcta * UNITS;
    const int warp = threadIdx.x >> 5;
    const int lane = threadIdx.x & 31;

    // --- smem rows: local rows {w*6+4, w*6+5} stored at smem row (w*2 + sub)
    for (int i = threadIdx.x; i < RSM * 8 * HID; i += GT) {
        int mrow = i >> 10;             // 0..15
        int c    = i & (HID - 1);
        int rr   = (mrow >> 1) * RPW + RREG + (mrow & 1);
        int grow = ((rr >> 4) << 10) + u0 + (rr & 15);
        wsh[i] = w_hh[(size_t)grow * HID + c];
    }
    if (threadIdx.x < RPC) {
        int rr = threadIdx.x;
        bsh[rr] = b_hh[((rr >> 4) << 10) + u0 + (rr & 15)];
    }

    // --- register rows: warp's local rows 0..3, this lane's 32 columns,
    // held as ulonglong2 (= 4 floats = 2 f32x2 operands each)
    ulonglong2 wreg[RREG][8];
    #pragma unroll
    for (int r = 0; r < RREG; r++) {
        const int rr   = warp * RPW + r;
        const int grow = ((rr >> 4) << 10) + u0 + (rr & 15);
        const float* gw = w_hh + (size_t)grow * HID + lane * 4;
        #pragma unroll
        for (int j = 0; j < 8; j++)
            wreg[r][j] = *(const ulonglong2*)(gw + j * 128);
    }
    __syncthreads();

    const float* wp = wsh + (warp * RSM) * HID + lane * 4;  // smem rows 4..5
    int* cnt_p = &g_cnt[dir][0];

    float hprev = 0.f;                  // warp 0 lanes < UNITS only

    for (int s = 0; s <= SEQ; s++) {
        const int t     = dir ? (SEQ - s) : (s - 1);
        const int girow = (s == 0) ? (SEQ + dir) : t;

        // gi prefetch (warp 0 lanes < 16; independent of h, overlaps poll)
        float gir = 0.f, giz = 0.f, gin = 0.f;
        if (threadIdx.x < UNITS) {
            const float* gp = g_GI + (size_t)girow * GATES + u0 + threadIdx.x;
            gir = __ldg(gp);
            giz = __ldg(gp + HID);
            gin = __ldg(gp + 2 * HID);
        }

        // Wait until all 64 CTAs of this direction finished step s-1.
        // EVERY thread polls with an ACQUIRE load (broadcast 4B sector);
        // ~90cyc spin backoff rides the worst-of-64 detect tail.
        if (s > 0) {
            const int need = s << 6;    // 64 * s
            if (ld_acq(cnt_p) < need) {
                do { spin_cycles(90); } while (ld_acq(cnt_p) < need);
            }
        }

        // load broadcast h as packed pairs (L2)
        const ulonglong2* hp = (const ulonglong2*)(&g_h[dir][s & 1][0]) + lane;
        ulonglong2 h2[8];
        #pragma unroll
        for (int j = 0; j < 8; j++) h2[j] = __ldcg(hp + 32 * j);

        // 6 dot products per warp in packed f32x2:
        // rows 0..3 from registers, rows 4..5 from smem
        unsigned long long accp[RPW] = {0ull, 0ull, 0ull, 0ull, 0ull, 0ull};
        #pragma unroll
        for (int j = 0; j < 8; j++) {
            const ulonglong2 hv = h2[j];
            #pragma unroll
            for (int r = 0; r < RREG; r++) {
                fma_f32x2(accp[r], wreg[r][j].x, hv.x);
                fma_f32x2(accp[r], wreg[r][j].y, hv.y);
            }
            #pragma unroll
            for (int r = 0; r < RSM; r++) {
                const ulonglong2 wv = *(const ulonglong2*)(wp + r * HID + j * 128);
                fma_f32x2(accp[RREG + r], wv.x, hv.x);
                fma_f32x2(accp[RREG + r], wv.y, hv.y);
            }
        }
        #pragma unroll
        for (int r = 0; r < RPW; r++) {
            float v = f32x2_hsum(accp[r]);
            v += __shfl_xor_sync(0xffffffffu, v, 16);
            v += __shfl_xor_sync(0xffffffffu, v, 8);
            v += __shfl_xor_sync(0xffffffffu, v, 4);
            v += __shfl_xor_sync(0xffffffffu, v, 2);
            v += __shfl_xor_sync(0xffffffffu, v, 1);
            if (lane == 0) sums[warp * RPW + r] = v;
        }
        __syncthreads();                // bar#1: sums ready for warp 0.
        // Warps 1-7 now proceed DIRECTLY to the next step's poll; they pass
        // poll(s+1) only after this CTA releases step s (warp 0, below),
        // which happens only after warp 0 has consumed sums[] of step s --
        // so sums[] reuse stays ordered without a second full barrier.

        if (warp == 0) {
            float hn = 0.f;
            if (lane < UNITS) {
                // fast gates: __expf (MUFU) + approx division
                float ar = gir + sums[lane]      + bsh[lane];
                float az = giz + sums[16 + lane] + bsh[16 + lane];
                float rg = __fdividef(1.f, 1.f + __expf(-ar));
                float zg = __fdividef(1.f, 1.f + __expf(-az));
                float an = gin + rg * (sums[32 + lane] + bsh[32 + lane]);
                float en = __expf(-2.f * an);
                float ng = __fdividef(1.f - en, 1.f + en);   // tanh(an)
                hn = (1.f - zg) * ng + zg * hprev;
                hprev = hn;
                __stcg(&g_h[dir][(s + 1) & 1][u0 + lane], hn);
            }
            // warp-0-scoped NAMED barrier: BAR-instruction cumulativity for
            // the 16 h stores above (same HW mechanism as __syncthreads,
            // without waiting on warps 1-7).
            asm volatile("bar.sync 1, 32;" ::: "memory");
            if (lane == 0) red_rel_add(cnt_p);  // release: publish h + count
            // out stores AFTER the publish (never read in-kernel)
            if (lane < UNITS && s >= 1) {
                const int u = u0 + lane;
                out[(size_t)HID + (size_t)t * (2 * HID) + dir * HID + u] = hn;
                if (dir == 1 && t == 0) out[u] = hn;   // h_b = hs_b[0]
            }
        }
    }
}

// ---------------------------------------------------------------------------
// launch
// ---------------------------------------------------------------------------
extern "C" void kernel_launch(void* const* d_in, const int* in_sizes, int n_in,
                              void* d_out, int out_size) {
    const void*  tokens = d_in[0];
    const float* emb    = (const float*)d_in[1];
    const float* w_ih   = (const float*)d_in[2];
    const float* w_hh   = (const float*)d_in[3];
    const float* b_ih   = (const float*)d_in[4];
    const float* b_hh   = (const float*)d_in[5];
    float* out = (float*)d_out;

    const int smem_bytes = (RSM * 8 * HID + 2 * RPC + 16) * (int)sizeof(float);
    cudaFuncSetAttribute(gru_seq_kernel,
                         cudaFuncAttributeMaxDynamicSharedMemorySize,
                         smem_bytes);

    dim3 ggrid(GATES / BN, (NROWS + BM - 1) / BM);
    gi_gemm_kernel<<<ggrid, 256>>>(tokens, emb, w_ih, b_ih);

    gru_seq_kernel<<<NCTA, GT, smem_bytes>>>(w_hh, b_hh, out);
}

// round 16
// speedup vs baseline: 1.1378x; 1.0730x over previous
#include <cuda_runtime.h>
#include <cstdint>

// ---------------------------------------------------------------------------
// EncoderGRU: bidirectional GRU, SEQ=4096, HIDDEN=EMBED=1024.
//
//   Phase 1+2 (one kernel): GI[t] = w_ih @ emb[tok[t]] + b_ih, fp32 SIMT GEMM,
//            inline token prep + recurrent-state reset by block (0,0).
//   Phase 3: persistent kernel, 128 CTAs (64 fwd / 64 bwd), each CTA owns 16
//            hidden units (48 w_hh rows; 4/warp in registers, 2/warp in smem).
//            r13 base (best: 10501us). Change this round: cooperative h
//            staging. Previously EVERY warp ldcg'd the full 4KB h -> the same
//            32 L2 lines fetched 512x/dir/step in a burst (slice storm).
//            Now each thread loads ONE float4 after its own acquire-poll,
//            stages to smem, one barrier, matvec reads h from smem
//            (conflict-free). 8x fewer L2 requests, 8x lower per-line fan-in.
//            Sync protocol unchanged (r12/r13-proven): producer
//            red.release.gpu after CTA barrier; consumer ld.acquire.gpu poll
//            + ~180cyc clock-spin backoff. Matvec: packed fma.rn.f32x2.
// ---------------------------------------------------------------------------

#define VOCAB   50257
#define HID     1024
#define SEQ     4096
#define NROWS   (SEQ + 2)       // 4098: +SOS row, +EOS row
#define GATES   3072

#define NCTA    128             // persistent grid (1 CTA/SM)
#define UNITS   16              // hidden units per CTA (64 CTAs/dir * 16 = 1024)
#define RPC     48              // weight rows per CTA (3 gates * 16 units)
#define GT      256             // threads in recurrent kernel
#define RPW     6               // rows per warp (8 warps * 6 = 48)
#define RREG    4               // rows per warp held in registers
#define RSM     2               // rows per warp streamed from smem (RPW-RREG)

// ---- global scratch (allocation-free: __device__ globals) ----
__device__ __align__(16)  float g_GI[(size_t)NROWS * GATES];    // ~50 MB
__device__ __align__(16)  float g_h[2][2][HID];                 // [dir][buf][unit]
__device__ __align__(128) int   g_cnt[2][32];                   // one 128B line per dir

// acquire-load: ordering + data in one instruction (pairs with red.release)
__device__ __forceinline__ int ld_acq(const int* p) {
    int v;
    asm volatile("ld.acquire.gpu.global.b32 %0, [%1];"
                 : "=r"(v) : "l"(p) : "memory");
    return v;
}
// release-reduction: publishes +1 with release semantics (cumulative through
// the preceding bar.sync -> covers the CTA's prior h stores)
__device__ __forceinline__ void red_rel_add(int* p) {
    asm volatile("red.release.gpu.global.add.u32 [%0], 1;"
                 :: "l"(p) : "memory");
}
// packed dual-fp32 FMA: d = a*b + d (elementwise on 2 packed floats)
__device__ __forceinline__ void fma_f32x2(unsigned long long& d,
                                          unsigned long long a,
                                          unsigned long long b) {
    asm("fma.rn.f32x2 %0, %1, %2, %3;" : "=l"(d) : "l"(a), "l"(b), "l"(d));
}
__device__ __forceinline__ float f32x2_hsum(unsigned long long v) {
    float lo, hi;
    asm("mov.b64 {%0, %1}, %2;" : "=f"(lo), "=f"(hi) : "l"(v));
    return lo + hi;
}

// Calibrated busy-wait: no memory traffic, bounded duration (SM clock cycles).
__device__ __forceinline__ void spin_cycles(long long n) {
    long long lim = clock64() + n;
    while (clock64() < lim) { }
}

// ---------------------------------------------------------------------------
// Phase 1+2: GI GEMM with inline token prep + state reset.
// C[m][n] = sum_k emb[tok[m]][k] * w_ih[n][k] + b_ih[n]
// BM=BN=128, BK=8, 256 threads, 8x8 microtile per thread.
// ---------------------------------------------------------------------------
#define BM 128
#define BN 128
#define BK 8

__global__ void __launch_bounds__(256) gi_gemm_kernel(
    const void*  __restrict__ tok_raw,
    const float* __restrict__ emb,
    const float* __restrict__ w_ih,
    const float* __restrict__ b_ih) {

    __shared__ float As[BK][BM];
    __shared__ float Bs[BK][BN];
    __shared__ int   mode64_sh;

    const int tid  = threadIdx.x;
    const int m0   = blockIdx.y * BM;
    const int n0   = blockIdx.x * BN;
    const int lrow = tid >> 1;          // 0..127
    const int lk   = (tid & 1) * 4;     // 0 or 4
    const int tx   = tid & 15;
    const int ty   = tid >> 4;

    // state reset (fresh every launch / graph replay) -- block (0,0) only
    if (blockIdx.x == 0 && blockIdx.y == 0) {
        for (int i = tid; i < 2 * 2 * HID; i += 256) ((float*)g_h)[i] = 0.f;
        if (tid < 64) ((int*)g_cnt)[tid] = 0;
    }

    // token dtype detection (per block; 8 loads, trivial)
    if (tid == 0) {
        // Genuine int64 tokens: every value < VOCAB (high word 0).
        // int32 data misread as int64: some 64-bit word >= VOCAB w.h.p.
        const unsigned long long* p = (const unsigned long long*)tok_raw;
        int m = 1;
        #pragma unroll
        for (int i = 0; i < 8; i++)
            if (p[i] >= (unsigned long long)VOCAB) m = 0;
        mode64_sh = m;
    }
    __syncthreads();
    const int mode64 = mode64_sh;

    // inline token fetch for this block's A row
    const int m = m0 + lrow;
    const float* arow_ptr = nullptr;
    if (m < NROWS) {
        int tok;
        if (m == SEQ)          tok = 0;   // SOS
        else if (m == SEQ + 1) tok = 1;   // EOS
        else tok = mode64 ? (int)((const long long*)tok_raw)[m]
                          : ((const int*)tok_raw)[m];
        arow_ptr = emb + (size_t)tok * HID;
    }
    const float* brow_ptr = w_ih + (size_t)(n0 + lrow) * HID;

    float acc[8][8];
    #pragma unroll
    for (int i = 0; i < 8; i++)
        #pragma unroll
        for (int j = 0; j < 8; j++) acc[i][j] = 0.f;

    for (int k0 = 0; k0 < HID; k0 += BK) {
        float4 a4 = make_float4(0.f, 0.f, 0.f, 0.f);
        if (arow_ptr) a4 = *(const float4*)(arow_ptr + k0 + lk);
        float4 b4 = *(const float4*)(brow_ptr + k0 + lk);
        As[lk + 0][lrow] = a4.x; As[lk + 1][lrow] = a4.y;
        As[lk + 2][lrow] = a4.z; As[lk + 3][lrow] = a4.w;
        Bs[lk + 0][lrow] = b4.x; Bs[lk + 1][lrow] = b4.y;
        Bs[lk + 2][lrow] = b4.z; Bs[lk + 3][lrow] = b4.w;
        __syncthreads();

        #pragma unroll
        for (int kk = 0; kk < BK; kk++) {
            float ra[8], rb[8];
            *(float4*)&ra[0] = *(const float4*)&As[kk][ty * 8];
            *(float4*)&ra[4] = *(const float4*)&As[kk][ty * 8 + 4];
            *(float4*)&rb[0] = *(const float4*)&Bs[kk][tx * 8];
            *(float4*)&rb[4] = *(const float4*)&Bs[kk][tx * 8 + 4];
            #pragma unroll
            for (int i = 0; i < 8; i++)
                #pragma unroll
                for (int j = 0; j < 8; j++)
                    acc[i][j] += ra[i] * rb[j];
        }
        __syncthreads();
    }

    float bias[8];
    *(float4*)&bias[0] = *(const float4*)(b_ih + n0 + tx * 8);
    *(float4*)&bias[4] = *(const float4*)(b_ih + n0 + tx * 8 + 4);

    #pragma unroll
    for (int i = 0; i < 8; i++) {
        int mm = m0 + ty * 8 + i;
        if (mm < NROWS) {
            float* gp = g_GI + (size_t)mm * GATES + n0 + tx * 8;
            float4 v0 = make_float4(acc[i][0] + bias[0], acc[i][1] + bias[1],
                                    acc[i][2] + bias[2], acc[i][3] + bias[3]);
            float4 v1 = make_float4(acc[i][4] + bias[4], acc[i][5] + bias[5],
                                    acc[i][6] + bias[6], acc[i][7] + bias[7]);
            *(float4*)gp       = v0;
            *(float4*)(gp + 4) = v1;
        }
    }
}

// ---------------------------------------------------------------------------
// Phase 3: persistent recurrent kernel (f32x2 matvec, smem h staging).
// Weight rows per warp: rows 0..3 in registers, rows 4..5 in smem.
// Global row for local row rr (0..47): ((rr>>4)<<10) + u0 + (rr&15).
// ---------------------------------------------------------------------------
__global__ void __launch_bounds__(GT, 1) gru_seq_kernel(
    const float* __restrict__ w_hh,
    const float* __restrict__ b_hh,
    float* __restrict__ out) {

    extern __shared__ float smem[];
    float* wsh  = smem;                     // 16 rows (2/warp) * HID
    float* hsm  = smem + (RSM * 8) * HID;   // staged h (HID floats)
    float* bsh  = hsm + HID;                // RPC biases
    float* sums = bsh + RPC;                // RPC partial sums

    const int cta  = blockIdx.x;
    const int dir  = cta >> 6;          // 0 = forward, 1 = backward
    const int lcta = cta & 63;
    const int u0   = lcta * UNITS;
    const int warp = threadIdx.x >> 5;
    const int lane = threadIdx.x & 31;

    // --- smem rows: local rows {w*6+4, w*6+5} stored at smem row (w*2 + sub)
    for (int i = threadIdx.x; i < RSM * 8 * HID; i += GT) {
        int mrow = i >> 10;             // 0..15
        int c    = i & (HID - 1);
        int rr   = (mrow >> 1) * RPW + RREG + (mrow & 1);
        int grow = ((rr >> 4) << 10) + u0 + (rr & 15);
        wsh[i] = w_hh[(size_t)grow * HID + c];
    }
    if (threadIdx.x < RPC) {
        int rr = threadIdx.x;
        bsh[rr] = b_hh[((rr >> 4) << 10) + u0 + (rr & 15)];
    }

    // --- register rows: warp's local rows 0..3, this lane's 32 columns,
    // held as ulonglong2 (= 4 floats = 2 f32x2 operands each)
    ulonglong2 wreg[RREG][8];
    #pragma unroll
    for (int r = 0; r < RREG; r++) {
        const int rr   = warp * RPW + r;
        const int grow = ((rr >> 4) << 10) + u0 + (rr & 15);
        const float* gw = w_hh + (size_t)grow * HID + lane * 4;
        #pragma unroll
        for (int j = 0; j < 8; j++)
            wreg[r][j] = *(const ulonglong2*)(gw + j * 128);
    }
    __syncthreads();

    const float* wp = wsh + (warp * RSM) * HID + lane * 4;  // smem rows 4..5
    int* cnt_p = &g_cnt[dir][0];

    float hprev = 0.f;                  // warp 0 lanes < UNITS only

    for (int s = 0; s <= SEQ; s++) {
        const int t     = dir ? (SEQ - s) : (s - 1);
        const int girow = (s == 0) ? (SEQ + dir) : t;

        // gi prefetch (warp 0 lanes < 16; independent of h, overlaps poll)
        float gir = 0.f, giz = 0.f, gin = 0.f;
        if (threadIdx.x < UNITS) {
            const float* gp = g_GI + (size_t)girow * GATES + u0 + threadIdx.x;
            gir = __ldg(gp);
            giz = __ldg(gp + HID);
            gin = __ldg(gp + 2 * HID);
        }

        // Wait until all 64 CTAs of this direction finished step s-1.
        // EVERY thread polls with an ACQUIRE load (broadcast 4B sector);
        // ~180cyc spin backoff keeps the counter line under slice capacity.
        if (s > 0) {
            const int need = s << 6;    // 64 * s
            if (ld_acq(cnt_p) < need) {
                do { spin_cycles(180); } while (ld_acq(cnt_p) < need);
            }
        }

        // --- cooperative h staging: ONE float4 per thread (32 L2 requests
        // per CTA instead of 256; per-line fan-in 64 instead of 512)
        {
            const float4* hg = (const float4*)(&g_h[dir][s & 1][0]);
            float4 hv = __ldcg(hg + threadIdx.x);
            *(float4*)(hsm + threadIdx.x * 4) = hv;
        }
        __syncthreads();                // staged h visible CTA-wide

        // 6 dot products per warp in packed f32x2; h from smem (conflict-
        // free 16B strides), rows 0..3 weights in regs, rows 4..5 in smem
        unsigned long long accp[RPW] = {0ull, 0ull, 0ull, 0ull, 0ull, 0ull};
        #pragma unroll
        for (int j = 0; j < 8; j++) {
            const ulonglong2 hv = *(const ulonglong2*)(hsm + lane * 4 + j * 128);
            #pragma unroll
            for (int r = 0; r < RREG; r++) {
                fma_f32x2(accp[r], wreg[r][j].x, hv.x);
                fma_f32x2(accp[r], wreg[r][j].y, hv.y);
            }
            #pragma unroll
            for (int r = 0; r < RSM; r++) {
                const ulonglong2 wv = *(const ulonglong2*)(wp + r * HID + j * 128);
                fma_f32x2(accp[RREG + r], wv.x, hv.x);
                fma_f32x2(accp[RREG + r], wv.y, hv.y);
            }
        }
        #pragma unroll
        for (int r = 0; r < RPW; r++) {
            float v = f32x2_hsum(accp[r]);
            v += __shfl_xor_sync(0xffffffffu, v, 16);
            v += __shfl_xor_sync(0xffffffffu, v, 8);
            v += __shfl_xor_sync(0xffffffffu, v, 4);
            v += __shfl_xor_sync(0xffffffffu, v, 2);
            v += __shfl_xor_sync(0xffffffffu, v, 1);
            if (lane == 0) sums[warp * RPW + r] = v;
        }
        __syncthreads();                // sums ready (h reads also complete)

        float hn = 0.f;
        if (threadIdx.x < UNITS) {
            const int i = threadIdx.x;
            // fast gates: __expf (MUFU) + approx division
            float ar = gir + sums[i]      + bsh[i];
            float az = giz + sums[16 + i] + bsh[16 + i];
            float rg = __fdividef(1.f, 1.f + __expf(-ar));
            float zg = __fdividef(1.f, 1.f + __expf(-az));
            float an = gin + rg * (sums[32 + i] + bsh[32 + i]);
            float en = __expf(-2.f * an);
            float ng = __fdividef(1.f - en, 1.f + en);   // tanh(an)
            hn = (1.f - zg) * ng + zg * hprev;
            hprev = hn;
            __stcg(&g_h[dir][(s + 1) & 1][u0 + i], hn);
        }
        __syncthreads();                // h stores ordered before the release
        if (threadIdx.x == 0) {
            red_rel_add(cnt_p);         // release-REDG: publish h + count
        }
        // out stores AFTER the publish (never read in-kernel)
        if (threadIdx.x < UNITS && s >= 1) {
            const int u = u0 + threadIdx.x;
            out[(size_t)HID + (size_t)t * (2 * HID) + dir * HID + u] = hn;
            if (dir == 1 && t == 0) out[u] = hn;    // h_b = hs_b[0]
        }
    }
}

// ---------------------------------------------------------------------------
// launch
// ---------------------------------------------------------------------------
extern "C" void kernel_launch(void* const* d_in, const int* in_sizes, int n_in,
                              void* d_out, int out_size) {
    const void*  tokens = d_in[0];
    const float* emb    = (const float*)d_in[1];
    const float* w_ih   = (const float*)d_in[2];
    const float* w_hh   = (const float*)d_in[3];
    const float* b_ih   = (const float*)d_in[4];
    const float* b_hh   = (const float*)d_in[5];
    float* out = (float*)d_out;

    const int smem_bytes = (RSM * 8 * HID + HID + 2 * RPC + 16) * (int)sizeof(float);
    cudaFuncSetAttribute(gru_seq_kernel,
                         cudaFuncAttributeMaxDynamicSharedMemorySize,
                         smem_bytes);

    dim3 ggrid(GATES / BN, (NROWS + BM - 1) / BM);
    gi_gemm_kernel<<<ggrid, 256>>>(tokens, emb, w_ih, b_ih);

    gru_seq_kernel<<<NCTA, GT, smem_bytes>>>(w_hh, b_hh, out);
}

// round 17
// speedup vs baseline: 1.1398x; 1.0017x over previous
#include <cuda_runtime.h>
#include <cstdint>

// ---------------------------------------------------------------------------
// EncoderGRU: bidirectional GRU, SEQ=4096, HIDDEN=EMBED=1024.
//
//   Phase 1+2 (one kernel): GI[t] = w_ih @ emb[tok[t]] + b_ih, fp32 SIMT GEMM,
//            inline token prep + recurrent-state reset by block (0,0).
//   Phase 3: persistent kernel, 128 CTAs (64 fwd / 64 bwd), each CTA owns 16
//            hidden units (48 w_hh rows; 4/warp in registers, 2/warp in smem).
//            r16 base (best: 10021us; smem h staging, f32x2 matvec, acquire
//            poll + release REDG, spin 180). Change this round (evaluated in
//            ISOLATION, unlike r15): the publish barrier is a warp-0-scoped
//            32-thread NAMED barrier (bar.sync 1,32) instead of a full
//            256-thread __syncthreads -- warps 1-7 go straight from the sums
//            barrier to the next step's poll; the release no longer waits on
//            7 idle warps. BAR-based cumulativity (r15-proven correct).
// ---------------------------------------------------------------------------

#define VOCAB   50257
#define HID     1024
#define SEQ     4096
#define NROWS   (SEQ + 2)       // 4098: +SOS row, +EOS row
#define GATES   3072

#define NCTA    128             // persistent grid (1 CTA/SM)
#define UNITS   16              // hidden units per CTA (64 CTAs/dir * 16 = 1024)
#define RPC     48              // weight rows per CTA (3 gates * 16 units)
#define GT      256             // threads in recurrent kernel
#define RPW     6               // rows per warp (8 warps * 6 = 48)
#define RREG    4               // rows per warp held in registers
#define RSM     2               // rows per warp streamed from smem (RPW-RREG)

// ---- global scratch (allocation-free: __device__ globals) ----
__device__ __align__(16)  float g_GI[(size_t)NROWS * GATES];    // ~50 MB
__device__ __align__(16)  float g_h[2][2][HID];                 // [dir][buf][unit]
__device__ __align__(128) int   g_cnt[2][32];                   // one 128B line per dir

// acquire-load: ordering + data in one instruction (pairs with red.release)
__device__ __forceinline__ int ld_acq(const int* p) {
    int v;
    asm volatile("ld.acquire.gpu.global.b32 %0, [%1];"
                 : "=r"(v) : "l"(p) : "memory");
    return v;
}
// release-reduction: publishes +1 with release semantics (cumulative through
// the preceding BAR -> covers warp 0's prior h stores)
__device__ __forceinline__ void red_rel_add(int* p) {
    asm volatile("red.release.gpu.global.add.u32 [%0], 1;"
                 :: "l"(p) : "memory");
}
// packed dual-fp32 FMA: d = a*b + d (elementwise on 2 packed floats)
__device__ __forceinline__ void fma_f32x2(unsigned long long& d,
                                          unsigned long long a,
                                          unsigned long long b) {
    asm("fma.rn.f32x2 %0, %1, %2, %3;" : "=l"(d) : "l"(a), "l"(b), "l"(d));
}
__device__ __forceinline__ float f32x2_hsum(unsigned long long v) {
    float lo, hi;
    asm("mov.b64 {%0, %1}, %2;" : "=f"(lo), "=f"(hi) : "l"(v));
    return lo + hi;
}

// Calibrated busy-wait: no memory traffic, bounded duration (SM clock cycles).
__device__ __forceinline__ void spin_cycles(long long n) {
    long long lim = clock64() + n;
    while (clock64() < lim) { }
}

// ---------------------------------------------------------------------------
// Phase 1+2: GI GEMM with inline token prep + state reset.
// C[m][n] = sum_k emb[tok[m]][k] * w_ih[n][k] + b_ih[n]
// BM=BN=128, BK=8, 256 threads, 8x8 microtile per thread.
// ---------------------------------------------------------------------------
#define BM 128
#define BN 128
#define BK 8

__global__ void __launch_bounds__(256) gi_gemm_kernel(
    const void*  __restrict__ tok_raw,
    const float* __restrict__ emb,
    const float* __restrict__ w_ih,
    const float* __restrict__ b_ih) {

    __shared__ float As[BK][BM];
    __shared__ float Bs[BK][BN];
    __shared__ int   mode64_sh;

    const int tid  = threadIdx.x;
    const int m0   = blockIdx.y * BM;
    const int n0   = blockIdx.x * BN;
    const int lrow = tid >> 1;          // 0..127
    const int lk   = (tid & 1) * 4;     // 0 or 4
    const int tx   = tid & 15;
    const int ty   = tid >> 4;

    // state reset (fresh every launch / graph replay) -- block (0,0) only
    if (blockIdx.x == 0 && blockIdx.y == 0) {
        for (int i = tid; i < 2 * 2 * HID; i += 256) ((float*)g_h)[i] = 0.f;
        if (tid < 64) ((int*)g_cnt)[tid] = 0;
    }

    // token dtype detection (per block; 8 loads, trivial)
    if (tid == 0) {
        // Genuine int64 tokens: every value < VOCAB (high word 0).
        // int32 data misread as int64: some 64-bit word >= VOCAB w.h.p.
        const unsigned long long* p = (const unsigned long long*)tok_raw;
        int m = 1;
        #pragma unroll
        for (int i = 0; i < 8; i++)
            if (p[i] >= (unsigned long long)VOCAB) m = 0;
        mode64_sh = m;
    }
    __syncthreads();
    const int mode64 = mode64_sh;

    // inline token fetch for this block's A row
    const int m = m0 + lrow;
    const float* arow_ptr = nullptr;
    if (m < NROWS) {
        int tok;
        if (m == SEQ)          tok = 0;   // SOS
        else if (m == SEQ + 1) tok = 1;   // EOS
        else tok = mode64 ? (int)((const long long*)tok_raw)[m]
                          : ((const int*)tok_raw)[m];
        arow_ptr = emb + (size_t)tok * HID;
    }
    const float* brow_ptr = w_ih + (size_t)(n0 + lrow) * HID;

    float acc[8][8];
    #pragma unroll
    for (int i = 0; i < 8; i++)
        #pragma unroll
        for (int j = 0; j < 8; j++) acc[i][j] = 0.f;

    for (int k0 = 0; k0 < HID; k0 += BK) {
        float4 a4 = make_float4(0.f, 0.f, 0.f, 0.f);
        if (arow_ptr) a4 = *(const float4*)(arow_ptr + k0 + lk);
        float4 b4 = *(const float4*)(brow_ptr + k0 + lk);
        As[lk + 0][lrow] = a4.x; As[lk + 1][lrow] = a4.y;
        As[lk + 2][lrow] = a4.z; As[lk + 3][lrow] = a4.w;
        Bs[lk + 0][lrow] = b4.x; Bs[lk + 1][lrow] = b4.y;
        Bs[lk + 2][lrow] = b4.z; Bs[lk + 3][lrow] = b4.w;
        __syncthreads();

        #pragma unroll
        for (int kk = 0; kk < BK; kk++) {
            float ra[8], rb[8];
            *(float4*)&ra[0] = *(const float4*)&As[kk][ty * 8];
            *(float4*)&ra[4] = *(const float4*)&As[kk][ty * 8 + 4];
            *(float4*)&rb[0] = *(const float4*)&Bs[kk][tx * 8];
            *(float4*)&rb[4] = *(const float4*)&Bs[kk][tx * 8 + 4];
            #pragma unroll
            for (int i = 0; i < 8; i++)
                #pragma unroll
                for (int j = 0; j < 8; j++)
                    acc[i][j] += ra[i] * rb[j];
        }
        __syncthreads();
    }

    float bias[8];
    *(float4*)&bias[0] = *(const float4*)(b_ih + n0 + tx * 8);
    *(float4*)&bias[4] = *(const float4*)(b_ih + n0 + tx * 8 + 4);

    #pragma unroll
    for (int i = 0; i < 8; i++) {
        int mm = m0 + ty * 8 + i;
        if (mm < NROWS) {
            float* gp = g_GI + (size_t)mm * GATES + n0 + tx * 8;
            float4 v0 = make_float4(acc[i][0] + bias[0], acc[i][1] + bias[1],
                                    acc[i][2] + bias[2], acc[i][3] + bias[3]);
            float4 v1 = make_float4(acc[i][4] + bias[4], acc[i][5] + bias[5],
                                    acc[i][6] + bias[6], acc[i][7] + bias[7]);
            *(float4*)gp       = v0;
            *(float4*)(gp + 4) = v1;
        }
    }
}

// ---------------------------------------------------------------------------
// Phase 3: persistent recurrent kernel (f32x2 matvec, smem h staging,
// warp-0 BAR publish).
// Weight rows per warp: rows 0..3 in registers, rows 4..5 in smem.
// Global row for local row rr (0..47): ((rr>>4)<<10) + u0 + (rr&15).
// ---------------------------------------------------------------------------
__global__ void __launch_bounds__(GT, 1) gru_seq_kernel(
    const float* __restrict__ w_hh,
    const float* __restrict__ b_hh,
    float* __restrict__ out) {

    extern __shared__ float smem[];
    float* wsh  = smem;                     // 16 rows (2/warp) * HID
    float* hsm  = smem + (RSM * 8) * HID;   // staged h (HID floats)
    float* bsh  = hsm + HID;                // RPC biases
    float* sums = bsh + RPC;                // RPC partial sums

    const int cta  = blockIdx.x;
    const int dir  = cta >> 6;          // 0 = forward, 1 = backward
    const int lcta = cta & 63;
    const int u0   = lcta * UNITS;
    const int warp = threadIdx.x >> 5;
    const int lane = threadIdx.x & 31;

    // --- smem rows: local rows {w*6+4, w*6+5} stored at smem row (w*2 + sub)
    for (int i = threadIdx.x; i < RSM * 8 * HID; i += GT) {
        int mrow = i >> 10;             // 0..15
        int c    = i & (HID - 1);
        int rr   = (mrow >> 1) * RPW + RREG + (mrow & 1);
        int grow = ((rr >> 4) << 10) + u0 + (rr & 15);
        wsh[i] = w_hh[(size_t)grow * HID + c];
    }
    if (threadIdx.x < RPC) {
        int rr = threadIdx.x;
        bsh[rr] = b_hh[((rr >> 4) << 10) + u0 + (rr & 15)];
    }

    // --- register rows: warp's local rows 0..3, this lane's 32 columns,
    // held as ulonglong2 (= 4 floats = 2 f32x2 operands each)
    ulonglong2 wreg[RREG][8];
    #pragma unroll
    for (int r = 0; r < RREG; r++) {
        const int rr   = warp * RPW + r;
        const int grow = ((rr >> 4) << 10) + u0 + (rr & 15);
        const float* gw = w_hh + (size_t)grow * HID + lane * 4;
        #pragma unroll
        for (int j = 0; j < 8; j++)
            wreg[r][j] = *(const ulonglong2*)(gw + j * 128);
    }
    __syncthreads();

    const float* wp = wsh + (warp * RSM) * HID + lane * 4;  // smem rows 4..5
    int* cnt_p = &g_cnt[dir][0];

    float hprev = 0.f;                  // warp 0 lanes < UNITS only

    for (int s = 0; s <= SEQ; s++) {
        const int t     = dir ? (SEQ - s) : (s - 1);
        const int girow = (s == 0) ? (SEQ + dir) : t;

        // gi prefetch (warp 0 lanes < 16; independent of h, overlaps poll)
        float gir = 0.f, giz = 0.f, gin = 0.f;
        if (threadIdx.x < UNITS) {
            const float* gp = g_GI + (size_t)girow * GATES + u0 + threadIdx.x;
            gir = __ldg(gp);
            giz = __ldg(gp + HID);
            gin = __ldg(gp + 2 * HID);
        }

        // Wait until all 64 CTAs of this direction finished step s-1.
        // EVERY thread polls with an ACQUIRE load (broadcast 4B sector);
        // ~180cyc spin backoff keeps the counter line under slice capacity.
        if (s > 0) {
            const int need = s << 6;    // 64 * s
            if (ld_acq(cnt_p) < need) {
                do { spin_cycles(180); } while (ld_acq(cnt_p) < need);
            }
        }

        // --- cooperative h staging: ONE float4 per thread (32 L2 requests
        // per CTA; per-line fan-in 64 instead of 512)
        {
            const float4* hg = (const float4*)(&g_h[dir][s & 1][0]);
            float4 hv = __ldcg(hg + threadIdx.x);
            *(float4*)(hsm + threadIdx.x * 4) = hv;
        }
        __syncthreads();                // staged h visible CTA-wide

        // 6 dot products per warp in packed f32x2; h from smem (conflict-
        // free 16B strides), rows 0..3 weights in regs, rows 4..5 in smem
        unsigned long long accp[RPW] = {0ull, 0ull, 0ull, 0ull, 0ull, 0ull};
        #pragma unroll
        for (int j = 0; j < 8; j++) {
            const ulonglong2 hv = *(const ulonglong2*)(hsm + lane * 4 + j * 128);
            #pragma unroll
            for (int r = 0; r < RREG; r++) {
                fma_f32x2(accp[r], wreg[r][j].x, hv.x);
                fma_f32x2(accp[r], wreg[r][j].y, hv.y);
            }
            #pragma unroll
            for (int r = 0; r < RSM; r++) {
                const ulonglong2 wv = *(const ulonglong2*)(wp + r * HID + j * 128);
                fma_f32x2(accp[RREG + r], wv.x, hv.x);
                fma_f32x2(accp[RREG + r], wv.y, hv.y);
            }
        }
        #pragma unroll
        for (int r = 0; r < RPW; r++) {
            float v = f32x2_hsum(accp[r]);
            v += __shfl_xor_sync(0xffffffffu, v, 16);
            v += __shfl_xor_sync(0xffffffffu, v, 8);
            v += __shfl_xor_sync(0xffffffffu, v, 4);
            v += __shfl_xor_sync(0xffffffffu, v, 2);
            v += __shfl_xor_sync(0xffffffffu, v, 1);
            if (lane == 0) sums[warp * RPW + r] = v;
        }
        __syncthreads();                // bar: sums ready for warp 0.
        // Warps 1-7 proceed DIRECTLY to the next step's poll: they can touch
        // hsm/sums for step s+1 only after poll(s+1) passes, which requires
        // this CTA's release below -- i.e. after warp 0 consumed sums(s).

        if (warp == 0) {
            float hn = 0.f;
            if (lane < UNITS) {
                // fast gates: __expf (MUFU) + approx division
                float ar = gir + sums[lane]      + bsh[lane];
                float az = giz + sums[16 + lane] + bsh[16 + lane];
                float rg = __fdividef(1.f, 1.f + __expf(-ar));
                float zg = __fdividef(1.f, 1.f + __expf(-az));
                float an = gin + rg * (sums[32 + lane] + bsh[32 + lane]);
                float en = __expf(-2.f * an);
                float ng = __fdividef(1.f - en, 1.f + en);   // tanh(an)
                hn = (1.f - zg) * ng + zg * hprev;
                hprev = hn;
                __stcg(&g_h[dir][(s + 1) & 1][u0 + lane], hn);
            }
            // warp-0-scoped NAMED barrier: BAR-instruction cumulativity for
            // the 16 h stores (same HW mechanism as __syncthreads) without
            // waking warps 1-7.
            asm volatile("bar.sync 1, 32;" ::: "memory");
            if (lane == 0) red_rel_add(cnt_p);  // release: publish h + count
            // out stores AFTER the publish (never read in-kernel)
            if (lane < UNITS && s >= 1) {
                const int u = u0 + lane;
                out[(size_t)HID + (size_t)t * (2 * HID) + dir * HID + u] = hn;
                if (dir == 1 && t == 0) out[u] = hn;   // h_b = hs_b[0]
            }
        }
    }
}

// ---------------------------------------------------------------------------
// launch
// ---------------------------------------------------------------------------
extern "C" void kernel_launch(void* const* d_in, const int* in_sizes, int n_in,
                              void* d_out, int out_size) {
    const void*  tokens = d_in[0];
    const float* emb    = (const float*)d_in[1];
    const float* w_ih   = (const float*)d_in[2];
    const float* w_hh   = (const float*)d_in[3];
    const float* b_ih   = (const float*)d_in[4];
    const float* b_hh   = (const float*)d_in[5];
    float* out = (float*)d_out;

    const int smem_bytes = (RSM * 8 * HID + HID + 2 * RPC + 16) * (int)sizeof(float);
    cudaFuncSetAttribute(gru_seq_kernel,
                         cudaFuncAttributeMaxDynamicSharedMemorySize,
                         smem_bytes);

    dim3 ggrid(GATES / BN, (NROWS + BM - 1) / BM);
    gi_gemm_kernel<<<ggrid, 256>>>(tokens, emb, w_ih, b_ih);

    gru_seq_kernel<<<NCTA, GT, smem_bytes>>>(w_hh, b_hh, out);
}